// round 10
// baseline (speedup 1.0000x reference)
#include <cuda_runtime.h>
#include <cuda_bf16.h>
#include <math.h>

// skipgram negative-sampling loss: one warp per batch element.
// R10: final probe -- 512-thread blocks (4096 blocks, 4 CTAs/SM, same
// 64 warps/SM) to halve per-wave CTA-tail spread and block atomics.
// All other structure identical to the converged R7 kernel
// (ncu 58.56-58.91us, DRAM 76.6-77.2%, regs 32, occ 91-98%).

#define D 128
#define NNEG 10
#define WARPS_PER_BLOCK 16
#define BLOCK_THREADS (WARPS_PER_BLOCK * 32)

__device__ __forceinline__ float log_sigmoid_f(float x) {
    return fminf(x, 0.0f) - log1pf(expf(-fabsf(x)));
}

__device__ __forceinline__ float dot4(const float4 a, const float4 b) {
    return a.x * b.x + a.y * b.y + a.z * b.z + a.w * b.w;
}

__global__ __launch_bounds__(BLOCK_THREADS, 4)
void skipgram_kernel(const float* __restrict__ u_w,
                     const float* __restrict__ v_w,
                     const int* __restrict__ u_pos,
                     const int* __restrict__ v_pos,
                     const int* __restrict__ v_neg,
                     float* __restrict__ out,
                     int B, float neg_inv_B) {
    const int gwarp = (blockIdx.x * BLOCK_THREADS + threadIdx.x) >> 5;
    const int lane  = threadIdx.x & 31;
    const int wid   = threadIdx.x >> 5;

    float val = 0.0f;
    if (gwarp < B) {
        const size_t ui = (size_t)u_pos[gwarp];
        const size_t vi = (size_t)v_pos[gwarp];

        // Neg indices: 10 ints, base 40B*gwarp -> always 8B aligned: 5x LDG.64.
        int nidx[NNEG];
        const int2* nb = reinterpret_cast<const int2*>(v_neg + (size_t)gwarp * NNEG);
        #pragma unroll
        for (int n = 0; n < NNEG / 2; n++) {
            const int2 a = nb[n];
            nidx[2 * n]     = a.x;
            nidx[2 * n + 1] = a.y;
        }

        // Row gathers: one warp fetches a full 512B row per LDG.128
        // (float4 per lane) -- perfectly coalesced, all sectors used.
        const float4 u4 = reinterpret_cast<const float4*>(u_w + ui * D)[lane];
        const float4 v4 = reinterpret_cast<const float4*>(v_w + vi * D)[lane];

        float pdot = dot4(u4, v4);

        float nacc = 0.0f;
        #pragma unroll
        for (int n = 0; n < NNEG; n++) {
            const float4 w4 = reinterpret_cast<const float4*>(v_w + (size_t)nidx[n] * D)[lane];
            nacc += dot4(u4, w4);
        }

        // One butterfly pass reduces both accumulators.
        #pragma unroll
        for (int off = 16; off > 0; off >>= 1) {
            pdot += __shfl_xor_sync(0xffffffffu, pdot, off);
            nacc += __shfl_xor_sync(0xffffffffu, nacc, off);
        }

        const float score  = pdot * (1.0f / (float)D);    // mean over D
        const float nscore = nacc * (1.0f / (float)NNEG); // mean over N
        val = (log_sigmoid_f(score) + log_sigmoid_f(-nscore)) * neg_inv_B;
    }

    // Block reduction -> one atomicAdd per block (4096 atomics total; noise).
    __shared__ float sm[WARPS_PER_BLOCK];
    if (lane == 0) sm[wid] = val;
    __syncthreads();
    if (threadIdx.x < WARPS_PER_BLOCK) {
        float v = sm[threadIdx.x];
        #pragma unroll
        for (int off = WARPS_PER_BLOCK / 2; off > 0; off >>= 1)
            v += __shfl_xor_sync(0xffffu, v, off);
        if (threadIdx.x == 0) atomicAdd(out, v);
    }
}

extern "C" void kernel_launch(void* const* d_in, const int* in_sizes, int n_in,
                              void* d_out, int out_size) {
    const float* u_w  = (const float*)d_in[0];
    const float* v_w  = (const float*)d_in[1];
    const int* u_pos  = (const int*)d_in[2];
    const int* v_pos  = (const int*)d_in[3];
    const int* v_neg  = (const int*)d_in[4];
    float* out        = (float*)d_out;

    const int B = in_sizes[2];

    cudaMemsetAsync(out, 0, sizeof(float), 0);

    const int warps = B;
    const int blocks = (warps + WARPS_PER_BLOCK - 1) / WARPS_PER_BLOCK;
    skipgram_kernel<<<blocks, BLOCK_THREADS>>>(u_w, v_w, u_pos, v_pos, v_neg,
                                               out, B, -1.0f / (float)B);
}

// round 11
// speedup vs baseline: 1.0318x; 1.0318x over previous
#include <cuda_runtime.h>
#include <cuda_bf16.h>
#include <math.h>

// skipgram negative-sampling loss: one warp per batch element. FINAL (R7 rev).
//
// Device-limited at the random-512B-gather ceiling:
//   ncu 58.56-58.91us, DRAM busy 76.6-77.2% (6.1 TB/s), occ 91-98%, regs 32.
// DRAM busy is invariant across 73-99% occupancy -> warp supply has slack;
// the ~23% idle is HBM3e activate/precharge overhead on random 512B bursts.
// Falsified levers: ILP-2 interleaved (63.5us), ILP-2 sequential (59.6),
// __ldcs hints (neutral), int2 idx loads (neutral), 512-thr blocks (59.6).
// Index sort/dedup traffic reduction costs more bandwidth than it saves.

#define D 128
#define NNEG 10
#define WARPS_PER_BLOCK 8
#define BLOCK_THREADS (WARPS_PER_BLOCK * 32)

__device__ __forceinline__ float log_sigmoid_f(float x) {
    return fminf(x, 0.0f) - log1pf(expf(-fabsf(x)));
}

__device__ __forceinline__ float dot4(const float4 a, const float4 b) {
    return a.x * b.x + a.y * b.y + a.z * b.z + a.w * b.w;
}

__global__ __launch_bounds__(BLOCK_THREADS, 7)
void skipgram_kernel(const float* __restrict__ u_w,
                     const float* __restrict__ v_w,
                     const int* __restrict__ u_pos,
                     const int* __restrict__ v_pos,
                     const int* __restrict__ v_neg,
                     float* __restrict__ out,
                     int B, float neg_inv_B) {
    const int gwarp = (blockIdx.x * BLOCK_THREADS + threadIdx.x) >> 5;
    const int lane  = threadIdx.x & 31;
    const int wid   = threadIdx.x >> 5;

    float val = 0.0f;
    if (gwarp < B) {
        const size_t ui = (size_t)u_pos[gwarp];
        const size_t vi = (size_t)v_pos[gwarp];

        // Neg indices: 10 ints, base 40B*gwarp -> always 8B aligned: 5x LDG.64.
        int nidx[NNEG];
        const int2* nb = reinterpret_cast<const int2*>(v_neg + (size_t)gwarp * NNEG);
        #pragma unroll
        for (int n = 0; n < NNEG / 2; n++) {
            const int2 a = nb[n];
            nidx[2 * n]     = a.x;
            nidx[2 * n + 1] = a.y;
        }

        // Row gathers: one warp fetches a full 512B row per LDG.128
        // (float4 per lane) -- perfectly coalesced, all sectors used.
        const float4 u4 = reinterpret_cast<const float4*>(u_w + ui * D)[lane];
        const float4 v4 = reinterpret_cast<const float4*>(v_w + vi * D)[lane];

        float pdot = dot4(u4, v4);

        float nacc = 0.0f;
        #pragma unroll
        for (int n = 0; n < NNEG; n++) {
            const float4 w4 = reinterpret_cast<const float4*>(v_w + (size_t)nidx[n] * D)[lane];
            nacc += dot4(u4, w4);
        }

        // One butterfly pass reduces both accumulators.
        #pragma unroll
        for (int off = 16; off > 0; off >>= 1) {
            pdot += __shfl_xor_sync(0xffffffffu, pdot, off);
            nacc += __shfl_xor_sync(0xffffffffu, nacc, off);
        }

        const float score  = pdot * (1.0f / (float)D);    // mean over D
        const float nscore = nacc * (1.0f / (float)NNEG); // mean over N
        val = (log_sigmoid_f(score) + log_sigmoid_f(-nscore)) * neg_inv_B;
    }

    // Block reduction -> one atomicAdd per block (8192 atomics total; noise).
    __shared__ float sm[WARPS_PER_BLOCK];
    if (lane == 0) sm[wid] = val;
    __syncthreads();
    if (threadIdx.x < WARPS_PER_BLOCK) {
        float v = sm[threadIdx.x];
        #pragma unroll
        for (int off = WARPS_PER_BLOCK / 2; off > 0; off >>= 1)
            v += __shfl_xor_sync(0xffu, v, off);
        if (threadIdx.x == 0) atomicAdd(out, v);
    }
}

extern "C" void kernel_launch(void* const* d_in, const int* in_sizes, int n_in,
                              void* d_out, int out_size) {
    const float* u_w  = (const float*)d_in[0];
    const float* v_w  = (const float*)d_in[1];
    const int* u_pos  = (const int*)d_in[2];
    const int* v_pos  = (const int*)d_in[3];
    const int* v_neg  = (const int*)d_in[4];
    float* out        = (float*)d_out;

    const int B = in_sizes[2];

    cudaMemsetAsync(out, 0, sizeof(float), 0);

    const int blocks = (B + WARPS_PER_BLOCK - 1) / WARPS_PER_BLOCK;
    skipgram_kernel<<<blocks, BLOCK_THREADS>>>(u_w, v_w, u_pos, v_pos, v_neg,
                                               out, B, -1.0f / (float)B);
}